// round 2
// baseline (speedup 1.0000x reference)
#include <cuda_runtime.h>
#include <math.h>

#define N_PTS 8192
#define DIM   2048
#define NCLS  751
#define KNN   6           // K+1 (k-reciprocal k=5 plus self)
#define GIN_ONE_PLUS_EPS 1.3f
#define BN_EPS 1e-5f

// ---------------- scratch (device globals: no runtime allocation) ----------
__device__ float g_xn [(size_t)N_PTS * DIM];
__device__ float g_sim[(size_t)N_PTS * N_PTS];
__device__ int   g_idx[(size_t)N_PTS * KNN];
__device__ float g_h0 [(size_t)N_PTS * DIM];
__device__ float g_h1 [(size_t)N_PTS * DIM];
__device__ float g_h2 [(size_t)N_PTS * DIM];
__device__ float g_hn [(size_t)N_PTS * DIM];
__device__ float g_scale[DIM];   // holds col-sum, then BN scale
__device__ float g_shift[DIM];   // holds col-sumsq, then BN shift

// ---------------- row L2 normalize ------------------------------------------
__global__ void normalize_kernel(const float* __restrict__ x) {
    int i = blockIdx.x;
    int tid = threadIdx.x;
    const float* xi = x + (size_t)i * DIM;
    float s = 0.f;
    for (int d = tid; d < DIM; d += 256) { float v = xi[d]; s += v * v; }
    __shared__ float sh[256];
    sh[tid] = s; __syncthreads();
    for (int o = 128; o > 0; o >>= 1) {
        if (tid < o) sh[tid] += sh[tid + o];
        __syncthreads();
    }
    float inv = 1.f / fmaxf(sqrtf(sh[0]), 1e-12f);
    float* out = g_xn + (size_t)i * DIM;
    for (int d = tid; d < DIM; d += 256) out[d] = xi[d] * inv;
}

// ---------------- fp32 SGEMM: C[M,Nc] = A[M,K] * B[Nc,K]^T (+bias)(+relu) ---
// 128x128 block tile, BK=8, 256 threads, 8x8 per thread (split 4+4).
__global__ __launch_bounds__(256)
void gemm_abt_kernel(const float* __restrict__ A, const float* __restrict__ B,
                     float* __restrict__ C, int M, int Nc, int Kd,
                     const float* __restrict__ bias, int relu, int symm)
{
    int bx = blockIdx.x, by = blockIdx.y;
    if (symm && bx > by) return;

    __shared__ float As[8][128];
    __shared__ float Bs[8][128];

    int tid = threadIdx.x;
    int tx = tid & 15;          // 0..15 (col group)
    int ty = tid >> 4;          // 0..15 (row group)

    int rowBase = by * 128;
    int colBase = bx * 128;

    int lr = tid >> 1;          // 0..127 load row within tile
    int lc = (tid & 1) * 4;     // 0 or 4  load col (k) within tile

    bool aval = (rowBase + lr) < M;
    bool bval = (colBase + lr) < Nc;
    const float* Aptr = A + (size_t)(rowBase + lr) * Kd + lc;
    const float* Bptr = B + (size_t)(colBase + lr) * Kd + lc;

    float acc[8][8];
#pragma unroll
    for (int i = 0; i < 8; ++i)
#pragma unroll
        for (int j = 0; j < 8; ++j) acc[i][j] = 0.f;

    for (int k0 = 0; k0 < Kd; k0 += 8) {
        float4 av = make_float4(0.f, 0.f, 0.f, 0.f);
        float4 bv = make_float4(0.f, 0.f, 0.f, 0.f);
        if (aval) av = *(const float4*)(Aptr + k0);
        if (bval) bv = *(const float4*)(Bptr + k0);
        As[lc + 0][lr] = av.x; As[lc + 1][lr] = av.y;
        As[lc + 2][lr] = av.z; As[lc + 3][lr] = av.w;
        Bs[lc + 0][lr] = bv.x; Bs[lc + 1][lr] = bv.y;
        Bs[lc + 2][lr] = bv.z; Bs[lc + 3][lr] = bv.w;
        __syncthreads();

#pragma unroll
        for (int kk = 0; kk < 8; ++kk) {
            float4 a0 = *(const float4*)&As[kk][ty * 4];
            float4 a1 = *(const float4*)&As[kk][64 + ty * 4];
            float4 b0 = *(const float4*)&Bs[kk][tx * 4];
            float4 b1 = *(const float4*)&Bs[kk][64 + tx * 4];
            float a[8] = {a0.x, a0.y, a0.z, a0.w, a1.x, a1.y, a1.z, a1.w};
            float b[8] = {b0.x, b0.y, b0.z, b0.w, b1.x, b1.y, b1.z, b1.w};
#pragma unroll
            for (int i = 0; i < 8; ++i)
#pragma unroll
                for (int j = 0; j < 8; ++j)
                    acc[i][j] = fmaf(a[i], b[j], acc[i][j]);
        }
        __syncthreads();
    }

    int rows[8], cols[8];
#pragma unroll
    for (int i = 0; i < 4; ++i) {
        rows[i]     = rowBase + ty * 4 + i;
        rows[i + 4] = rowBase + 64 + ty * 4 + i;
        cols[i]     = colBase + tx * 4 + i;
        cols[i + 4] = colBase + 64 + tx * 4 + i;
    }
#pragma unroll
    for (int i = 0; i < 8; ++i) {
#pragma unroll
        for (int j = 0; j < 8; ++j) {
            int r = rows[i], c = cols[j];
            if (r < M && c < Nc) {
                float v = acc[i][j];
                if (bias) v += bias[c];
                if (relu) v = fmaxf(v, 0.f);
                C[(size_t)r * Nc + c] = v;
                if (symm && bx < by)             // mirror tile (Nc == M here)
                    C[(size_t)c * Nc + r] = v;
            }
        }
    }
}

// ---------------- exact per-row top-6 (largest sim, tie -> lower index) -----
__device__ __forceinline__ bool better(float v1, int i1, float v2, int i2) {
    return (v1 > v2) || (v1 == v2 && i1 < i2);
}

__global__ void topk_kernel() {
    int i = blockIdx.x;
    int tid = threadIdx.x;      // 128 threads
    const float* row = g_sim + (size_t)i * N_PTS;

    float bv[KNN]; int bi[KNN];
#pragma unroll
    for (int c = 0; c < KNN; ++c) { bv[c] = -INFINITY; bi[c] = 0x7fffffff; }

    for (int j = tid; j < N_PTS; j += 128) {
        float v = row[j];
        if (better(v, j, bv[KNN - 1], bi[KNN - 1])) {
            bv[KNN - 1] = v; bi[KNN - 1] = j;
#pragma unroll
            for (int c = KNN - 1; c > 0; --c) {
                if (better(bv[c], bi[c], bv[c - 1], bi[c - 1])) {
                    float tv = bv[c]; bv[c] = bv[c - 1]; bv[c - 1] = tv;
                    int   ti = bi[c]; bi[c] = bi[c - 1]; bi[c - 1] = ti;
                }
            }
        }
    }

    __shared__ float sv[128 * KNN];
    __shared__ int   si[128 * KNN];
    __shared__ float rv[128];
    __shared__ int   ri[128];
    __shared__ int   rp[128];
#pragma unroll
    for (int c = 0; c < KNN; ++c) { sv[tid * KNN + c] = bv[c]; si[tid * KNN + c] = bi[c]; }
    __syncthreads();

    for (int r = 0; r < KNN; ++r) {
        float best = -INFINITY; int besti = 0x7fffffff; int bestp = -1;
        for (int p = tid; p < 128 * KNN; p += 128) {
            if (better(sv[p], si[p], best, besti)) { best = sv[p]; besti = si[p]; bestp = p; }
        }
        rv[tid] = best; ri[tid] = besti; rp[tid] = bestp;
        __syncthreads();
        for (int o = 64; o > 0; o >>= 1) {
            if (tid < o) {
                if (better(rv[tid + o], ri[tid + o], rv[tid], ri[tid])) {
                    rv[tid] = rv[tid + o]; ri[tid] = ri[tid + o]; rp[tid] = rp[tid + o];
                }
            }
            __syncthreads();
        }
        if (tid == 0) {
            g_idx[(size_t)i * KNN + r] = ri[0];
            sv[rp[0]] = -INFINITY; si[rp[0]] = 0x7fffffff;
        }
        __syncthreads();
    }
}

// ---------------- k-reciprocal mask + GIN aggregation -----------------------
__global__ void aggr_kernel(const float* __restrict__ x) {
    int i = blockIdx.x;
    int tid = threadIdx.x;      // 256
    __shared__ int nb[KNN];
    __shared__ int ok[KNN];
    if (tid < KNN) {
        int j = g_idx[(size_t)i * KNN + tid];
        nb[tid] = j;
        int r = 0;
#pragma unroll
        for (int t = 0; t < KNN; ++t) r |= (g_idx[(size_t)j * KNN + t] == i);
        ok[tid] = r;
    }
    __syncthreads();
    for (int d = tid; d < DIM; d += 256) {
        float acc = GIN_ONE_PLUS_EPS * x[(size_t)i * DIM + d];
#pragma unroll
        for (int c = 0; c < KNN; ++c)
            if (ok[c]) acc += x[(size_t)nb[c] * DIM + d];
        g_h0[(size_t)i * DIM + d] = acc;
    }
}

// ---------------- BatchNorm (training-mode batch stats) ---------------------
__global__ void bn_zero_kernel() {
    int c = blockIdx.x * 256 + threadIdx.x;
    if (c < DIM) { g_scale[c] = 0.f; g_shift[c] = 0.f; }
}

__global__ void bn_stats_kernel() {
    int c  = blockIdx.x * 256 + threadIdx.x;   // column
    int r0 = blockIdx.y * 256;                 // row chunk
    float s = 0.f, q = 0.f;
    for (int r = r0; r < r0 + 256; ++r) {
        float v = g_h2[(size_t)r * DIM + c];
        s += v; q += v * v;
    }
    atomicAdd(&g_scale[c], s);
    atomicAdd(&g_shift[c], q);
}

__global__ void bn_finalize_kernel(const float* __restrict__ gamma,
                                   const float* __restrict__ beta) {
    int c = blockIdx.x * 256 + threadIdx.x;
    if (c >= DIM) return;
    const float invN = 1.f / (float)N_PTS;
    float mean = g_scale[c] * invN;
    float var  = g_shift[c] * invN - mean * mean;
    float sc   = gamma[c] * rsqrtf(var + BN_EPS);
    g_scale[c] = sc;
    g_shift[c] = beta[c] - mean * sc;
}

__global__ void bn_apply_kernel() {
    size_t idx = (size_t)blockIdx.x * 256 + threadIdx.x;
    int c = (int)(idx & (DIM - 1));
    g_hn[idx] = g_h2[idx] * g_scale[c] + g_shift[c];
}

// ---------------- launch ----------------------------------------------------
extern "C" void kernel_launch(void* const* d_in, const int* in_sizes, int n_in,
                              void* d_out, int out_size) {
    const float* x     = (const float*)d_in[0];
    const float* w1    = (const float*)d_in[1];
    const float* b1    = (const float*)d_in[2];
    const float* w2    = (const float*)d_in[3];
    const float* b2    = (const float*)d_in[4];
    const float* gamma = (const float*)d_in[5];
    const float* beta  = (const float*)d_in[6];
    const float* wc    = (const float*)d_in[7];
    float* out = (float*)d_out;

    float *p_xn, *p_sim, *p_h0, *p_h1, *p_h2, *p_hn;
    cudaGetSymbolAddress((void**)&p_xn,  g_xn);
    cudaGetSymbolAddress((void**)&p_sim, g_sim);
    cudaGetSymbolAddress((void**)&p_h0,  g_h0);
    cudaGetSymbolAddress((void**)&p_h1,  g_h1);
    cudaGetSymbolAddress((void**)&p_h2,  g_h2);
    cudaGetSymbolAddress((void**)&p_hn,  g_hn);

    // 1) row-normalize
    normalize_kernel<<<N_PTS, 256>>>(x);

    // 2) similarity matrix (symmetric: compute lower-tri blocks, mirror-store)
    gemm_abt_kernel<<<dim3(64, 64), 256>>>(p_xn, p_xn, p_sim,
                                           N_PTS, N_PTS, DIM, nullptr, 0, 1);

    // 3) exact top-6 per row (tie-break: lower index, matches lax.top_k)
    topk_kernel<<<N_PTS, 128>>>();

    // 4) k-reciprocal mask + GIN aggregation -> h0
    aggr_kernel<<<N_PTS, 256>>>(x);

    // 5) MLP layer 1: relu(h0 @ w1^T + b1)
    gemm_abt_kernel<<<dim3(16, 64), 256>>>(p_h0, w1, p_h1,
                                           N_PTS, DIM, DIM, b1, 1, 0);

    // 6) MLP layer 2: h1 @ w2^T + b2
    gemm_abt_kernel<<<dim3(16, 64), 256>>>(p_h1, w2, p_h2,
                                           N_PTS, DIM, DIM, b2, 0, 0);

    // 7) BatchNorm (batch statistics)
    bn_zero_kernel<<<(DIM + 255) / 256, 256>>>();
    bn_stats_kernel<<<dim3(DIM / 256, N_PTS / 256), 256>>>();
    bn_finalize_kernel<<<(DIM + 255) / 256, 256>>>(gamma, beta);
    bn_apply_kernel<<<(unsigned)(((size_t)N_PTS * DIM) / 256), 256>>>();

    // 8) classifier: hn @ wc^T -> d_out [8192, 751]
    gemm_abt_kernel<<<dim3((NCLS + 127) / 128, 64), 256>>>(p_hn, wc, out,
                                                           N_PTS, NCLS, DIM,
                                                           nullptr, 0, 0);
}

// round 5
// speedup vs baseline: 2.2926x; 2.2926x over previous
#include <cuda_runtime.h>
#include <cuda_bf16.h>
#include <cstdint>
#include <math.h>

#define N_PTS 8192
#define DIM   2048
#define NCLS  751
#define KNN   6
#define CAND  16
#define GIN_ONE_PLUS_EPS 1.3f
#define BN_EPS 1e-5f

// ---------------- scratch ----------------------------------------------------
__device__ float g_xn [(size_t)N_PTS * DIM];
__device__ unsigned short g_xh [(size_t)N_PTS * DIM];     // bf16 of xn
__device__ float g_sim[(size_t)N_PTS * N_PTS];
__device__ int   g_cand[(size_t)N_PTS * CAND];
__device__ int   g_idx[(size_t)N_PTS * KNN];
__device__ float g_h0 [(size_t)N_PTS * DIM];
__device__ float g_h1 [(size_t)N_PTS * DIM];
__device__ float g_h2 [(size_t)N_PTS * DIM];
__device__ float g_hn [(size_t)N_PTS * DIM];
__device__ unsigned short g_sh [(size_t)N_PTS * DIM];     // activation split hi
__device__ unsigned short g_sl [(size_t)N_PTS * DIM];     // activation split lo
__device__ unsigned short g_w1h[(size_t)DIM * DIM], g_w1l[(size_t)DIM * DIM];
__device__ unsigned short g_w2h[(size_t)DIM * DIM], g_w2l[(size_t)DIM * DIM];
__device__ unsigned short g_wch[(size_t)NCLS * DIM], g_wcl[(size_t)NCLS * DIM];
__device__ float g_scale[DIM];
__device__ float g_shift[DIM];

// ---------------- helpers ----------------------------------------------------
__device__ __forceinline__ uint32_t smem_to_u32(const void* p) {
    uint32_t a;
    asm("{ .reg .u64 t; cvta.to.shared.u64 t, %1; cvt.u32.u64 %0, t; }" : "=r"(a) : "l"(p));
    return a;
}

__device__ __forceinline__ void cp_async16(uint32_t dst, const void* src, int valid) {
    asm volatile("cp.async.cg.shared.global [%0], [%1], 16, %2;"
                 :: "r"(dst), "l"(src), "r"(valid ? 16 : 0) : "memory");
}
__device__ __forceinline__ void cp_commit() {
    asm volatile("cp.async.commit_group;" ::: "memory");
}
template <int N>
__device__ __forceinline__ void cp_wait() {
    asm volatile("cp.async.wait_group %0;" :: "n"(N) : "memory");
}

__device__ __forceinline__ void ldm_x4(uint32_t* r, uint32_t addr) {
    asm volatile("ldmatrix.sync.aligned.m8n8.x4.shared.b16 {%0,%1,%2,%3}, [%4];"
                 : "=r"(r[0]), "=r"(r[1]), "=r"(r[2]), "=r"(r[3]) : "r"(addr));
}

__device__ __forceinline__ void mma16816(float* d, const uint32_t* a, uint32_t b0, uint32_t b1) {
    asm volatile("mma.sync.aligned.m16n8k16.row.col.f32.bf16.bf16.f32 "
                 "{%0,%1,%2,%3}, {%4,%5,%6,%7}, {%8,%9}, {%0,%1,%2,%3};"
                 : "+f"(d[0]), "+f"(d[1]), "+f"(d[2]), "+f"(d[3])
                 : "r"(a[0]), "r"(a[1]), "r"(a[2]), "r"(a[3]), "r"(b0), "r"(b1));
}

// ---------------- bf16 mma.sync GEMM: C[M,Nc] = A[M,K] * B[Nc,K]^T ----------
// 128x128 tile, BK=64, 256 thr (8 warps, 4x2; warp tile 32x64), cp.async
// double buffer, XOR-swizzled smem, ldmatrix.x4 operands.
// three=1: acc = Ah*Bh + Ah*Bl + Al*Bh (hi/lo bf16 split, fp32 accum).
// symm=1 : only bx<=by tiles computed; mirror tile stored via smem transpose.
#define SMEM_GEMM 66048   // max(2*32768 pipeline, 128*129*4 transpose stage)

__global__ __launch_bounds__(256, 2)
void gemm_mma(const __nv_bfloat16* __restrict__ Ah, const __nv_bfloat16* __restrict__ Al,
              const __nv_bfloat16* __restrict__ Bh, const __nv_bfloat16* __restrict__ Bl,
              float* __restrict__ C, int M, int Nc, int Kd,
              const float* __restrict__ bias, int relu, int three, int symm)
{
    const int bx = blockIdx.x, by = blockIdx.y;
    if (symm && bx > by) return;

    extern __shared__ char smem[];
    const uint32_t sb = smem_to_u32(smem);
    const int tid = threadIdx.x;
    const int lane = tid & 31;
    const int wid = tid >> 5;
    const int wm = wid & 3;          // 0..3  (M dir, 32 rows each)
    const int wn = wid >> 2;         // 0..1  (N dir, 64 cols each)
    const int wRow = wm * 32, wCol = wn * 64;

    const int rowBase = by * 128;
    const int colBase = bx * 128;
    const int kcount = Kd / 64;
    const int nchunk = (three ? 3 : 1) * kcount;

    float acc[2][8][4];
#pragma unroll
    for (int i = 0; i < 2; ++i)
#pragma unroll
        for (int j = 0; j < 8; ++j)
#pragma unroll
            for (int q = 0; q < 4; ++q) acc[i][j][q] = 0.f;

    // ---- async chunk loader (A: 16KB, B: 16KB per buffer) ----
    auto load_chunk = [&](int c) {
        const int pass = three ? (c / kcount) : 0;
        const int k0 = (three ? (c % kcount) : c) * 64;
        const __nv_bfloat16* As = (pass == 2) ? Al : Ah;
        const __nv_bfloat16* Bs = (pass == 1) ? Bl : Bh;
        const uint32_t base = sb + (uint32_t)(c & 1) * 32768u;
#pragma unroll
        for (int i = 0; i < 4; ++i) {
            const int u = tid + i * 256;           // 0..1023 over A tile
            const int r = u >> 3, ku = u & 7;
            const int grow = rowBase + r;
            cp_async16(base + (uint32_t)(r * 8 + (ku ^ (r & 7))) * 16,
                       As + (size_t)grow * Kd + k0 + ku * 8, grow < M);
        }
#pragma unroll
        for (int i = 0; i < 4; ++i) {
            const int u = tid + i * 256;           // over B tile
            const int r = u >> 3, ku = u & 7;
            const int grow = colBase + r;
            cp_async16(base + 16384u + (uint32_t)(r * 8 + (ku ^ (r & 7))) * 16,
                       Bs + (size_t)grow * Kd + k0 + ku * 8, grow < Nc);
        }
        cp_commit();
    };

    load_chunk(0);

    for (int c = 0; c < nchunk; ++c) {
        if (c + 1 < nchunk) { load_chunk(c + 1); cp_wait<1>(); }
        else                { cp_wait<0>(); }
        __syncthreads();

        const uint32_t base = sb + (uint32_t)(c & 1) * 32768u;
#pragma unroll
        for (int s = 0; s < 4; ++s) {              // four k16 steps
            uint32_t a[2][4];
#pragma unroll
            for (int i = 0; i < 2; ++i) {
                const int r = wRow + i * 16 + (lane & 15);
                const int ku = s * 2 + (lane >> 4);
                ldm_x4(a[i], base + (uint32_t)(r * 8 + (ku ^ (r & 7))) * 16);
            }
            uint32_t bf[4][4];
#pragma unroll
            for (int j = 0; j < 4; ++j) {
                const int rn = wCol + j * 16 + (lane & 7) + ((lane >> 4) << 3);
                const int ku = s * 2 + ((lane >> 3) & 1);
                ldm_x4(bf[j], base + 16384u + (uint32_t)(rn * 8 + (ku ^ (rn & 7))) * 16);
            }
#pragma unroll
            for (int i = 0; i < 2; ++i)
#pragma unroll
                for (int j = 0; j < 4; ++j) {
                    mma16816(acc[i][j * 2 + 0], a[i], bf[j][0], bf[j][1]);
                    mma16816(acc[i][j * 2 + 1], a[i], bf[j][2], bf[j][3]);
                }
        }
        __syncthreads();
    }

    // ---- epilogue ----
    const int r0 = rowBase + wRow + (lane >> 2);
    const int lr0 = wRow + (lane >> 2);
#pragma unroll
    for (int i = 0; i < 2; ++i) {
#pragma unroll
        for (int j = 0; j < 8; ++j) {
            const int col = colBase + wCol + j * 8 + (lane & 3) * 2;
            const int row = r0 + i * 16;
#pragma unroll
            for (int h = 0; h < 2; ++h) {          // h=0: row, h=1: row+8
                const int rr = row + h * 8;
                if (rr < M) {
                    float v0 = acc[i][j][h * 2 + 0];
                    float v1 = acc[i][j][h * 2 + 1];
                    if (bias) {
                        if (col     < Nc) v0 += __ldg(bias + col);
                        if (col + 1 < Nc) v1 += __ldg(bias + col + 1);
                    }
                    if (relu) { v0 = fmaxf(v0, 0.f); v1 = fmaxf(v1, 0.f); }
                    if (col     < Nc) C[(size_t)rr * Nc + col]     = v0;
                    if (col + 1 < Nc) C[(size_t)rr * Nc + col + 1] = v1;
                }
            }
        }
    }

    // ---- symmetric mirror tile via smem transpose (coalesced both ways) ----
    if (symm && bx < by) {
        float* sc = (float*)smem;                  // [128][129]
#pragma unroll
        for (int i = 0; i < 2; ++i)
#pragma unroll
            for (int j = 0; j < 8; ++j) {
                const int lc = wCol + j * 8 + (lane & 3) * 2;
                const int lrr = lr0 + i * 16;
                sc[(lrr    ) * 129 + lc    ] = acc[i][j][0];
                sc[(lrr    ) * 129 + lc + 1] = acc[i][j][1];
                sc[(lrr + 8) * 129 + lc    ] = acc[i][j][2];
                sc[(lrr + 8) * 129 + lc + 1] = acc[i][j][3];
            }
        __syncthreads();
        const int tr = tid >> 1;                   // transposed-tile row 0..127
        const int half = (tid & 1) * 64;
        float* drow = C + (size_t)(colBase + tr) * Nc + rowBase + half;
#pragma unroll 8
        for (int i2 = 0; i2 < 64; ++i2)
            drow[i2] = sc[(half + i2) * 129 + tr];
    }
}

// ---------------- row L2 normalize (fp32 + bf16 copy) ------------------------
__global__ void normalize_kernel(const float* __restrict__ x) {
    int i = blockIdx.x;
    int tid = threadIdx.x;
    const float* xi = x + (size_t)i * DIM;
    float s = 0.f;
    for (int d = tid; d < DIM; d += 256) { float v = xi[d]; s += v * v; }
    __shared__ float sh[256];
    sh[tid] = s; __syncthreads();
    for (int o = 128; o > 0; o >>= 1) {
        if (tid < o) sh[tid] += sh[tid + o];
        __syncthreads();
    }
    float inv = 1.f / fmaxf(sqrtf(sh[0]), 1e-12f);
    float* out = g_xn + (size_t)i * DIM;
    __nv_bfloat16* outh = (__nv_bfloat16*)(g_xh) + (size_t)i * DIM;
    for (int d = tid; d < DIM; d += 256) {
        float v = xi[d] * inv;
        out[d] = v;
        outh[d] = __float2bfloat16(v);
    }
}

// ---------------- bf16 hi/lo split -------------------------------------------
__global__ void split_kernel(const float* __restrict__ src,
                             unsigned short* __restrict__ hi,
                             unsigned short* __restrict__ lo, size_t n) {
    size_t i = (size_t)blockIdx.x * 256 + threadIdx.x;
    if (i >= n) return;
    float v = src[i];
    __nv_bfloat16 h = __float2bfloat16(v);
    ((__nv_bfloat16*)hi)[i] = h;
    ((__nv_bfloat16*)lo)[i] = __float2bfloat16(v - __bfloat162float(h));
}

// ---------------- exact per-row top-16 candidates ----------------------------
__device__ __forceinline__ bool better(float v1, int i1, float v2, int i2) {
    return (v1 > v2) || (v1 == v2 && i1 < i2);
}

__global__ void topk_kernel() {
    int i = blockIdx.x;
    int tid = threadIdx.x;      // 128 threads
    const float* row = g_sim + (size_t)i * N_PTS;

    float bv[CAND]; int bi[CAND];
#pragma unroll
    for (int c = 0; c < CAND; ++c) { bv[c] = -INFINITY; bi[c] = 0x7fffffff; }

    for (int j = tid; j < N_PTS; j += 128) {
        float v = row[j];
        if (better(v, j, bv[CAND - 1], bi[CAND - 1])) {
            bv[CAND - 1] = v; bi[CAND - 1] = j;
#pragma unroll
            for (int c = CAND - 1; c > 0; --c) {
                if (better(bv[c], bi[c], bv[c - 1], bi[c - 1])) {
                    float tv = bv[c]; bv[c] = bv[c - 1]; bv[c - 1] = tv;
                    int   ti = bi[c]; bi[c] = bi[c - 1]; bi[c - 1] = ti;
                }
            }
        }
    }

    __shared__ float sv[128 * CAND];
    __shared__ int   si[128 * CAND];
    __shared__ float rv[128];
    __shared__ int   ri[128];
    __shared__ int   rp[128];
#pragma unroll
    for (int c = 0; c < CAND; ++c) { sv[tid * CAND + c] = bv[c]; si[tid * CAND + c] = bi[c]; }
    __syncthreads();

    for (int r = 0; r < CAND; ++r) {
        float best = -INFINITY; int besti = 0x7fffffff; int bestp = -1;
        for (int p = tid; p < 128 * CAND; p += 128) {
            if (better(sv[p], si[p], best, besti)) { best = sv[p]; besti = si[p]; bestp = p; }
        }
        rv[tid] = best; ri[tid] = besti; rp[tid] = bestp;
        __syncthreads();
        for (int o = 64; o > 0; o >>= 1) {
            if (tid < o) {
                if (better(rv[tid + o], ri[tid + o], rv[tid], ri[tid])) {
                    rv[tid] = rv[tid + o]; ri[tid] = ri[tid + o]; rp[tid] = rp[tid + o];
                }
            }
            __syncthreads();
        }
        if (tid == 0) {
            g_cand[(size_t)i * CAND + r] = ri[0];
            sv[rp[0]] = -INFINITY; si[rp[0]] = 0x7fffffff;
        }
        __syncthreads();
    }
}

// ---------------- exact fp32 rescore of 16 candidates -> top-6 ---------------
__global__ void rescore_kernel() {
    int i = blockIdx.x;
    int tid = threadIdx.x;      // 256
    int wid = tid >> 5, lane = tid & 31;
    __shared__ float xi[DIM];
    __shared__ int cand[CAND];
    __shared__ float red[CAND][8];
    for (int d = tid; d < DIM; d += 256) xi[d] = g_xn[(size_t)i * DIM + d];
    if (tid < CAND) cand[tid] = g_cand[(size_t)i * CAND + tid];
    __syncthreads();

    float acc[CAND];
#pragma unroll
    for (int c = 0; c < CAND; ++c) acc[c] = 0.f;
    for (int d = tid; d < DIM; d += 256) {
        float xv = xi[d];
#pragma unroll
        for (int c = 0; c < CAND; ++c)
            acc[c] += xv * g_xn[(size_t)cand[c] * DIM + d];
    }
#pragma unroll
    for (int c = 0; c < CAND; ++c) {
#pragma unroll
        for (int o = 16; o > 0; o >>= 1)
            acc[c] += __shfl_xor_sync(0xffffffffu, acc[c], o);
        if (lane == 0) red[c][wid] = acc[c];
    }
    __syncthreads();
    if (tid == 0) {
        float cv[CAND]; int ci[CAND];
#pragma unroll
        for (int c = 0; c < CAND; ++c) {
            float s = 0.f;
#pragma unroll
            for (int w = 0; w < 8; ++w) s += red[c][w];
            cv[c] = s; ci[c] = cand[c];
        }
        for (int r = 0; r < KNN; ++r) {
            int bp = r;
            for (int c = r + 1; c < CAND; ++c)
                if (better(cv[c], ci[c], cv[bp], ci[bp])) bp = c;
            float tv = cv[r]; cv[r] = cv[bp]; cv[bp] = tv;
            int   ti = ci[r]; ci[r] = ci[bp]; ci[bp] = ti;
            g_idx[(size_t)i * KNN + r] = ci[r];
        }
    }
}

// ---------------- k-reciprocal mask + GIN aggregation ------------------------
__global__ void aggr_kernel(const float* __restrict__ x) {
    int i = blockIdx.x;
    int tid = threadIdx.x;      // 256
    __shared__ int nb[KNN];
    __shared__ int ok[KNN];
    if (tid < KNN) {
        int j = g_idx[(size_t)i * KNN + tid];
        nb[tid] = j;
        int r = 0;
#pragma unroll
        for (int t = 0; t < KNN; ++t) r |= (g_idx[(size_t)j * KNN + t] == i);
        ok[tid] = r;
    }
    __syncthreads();
    for (int d = tid; d < DIM; d += 256) {
        float acc = GIN_ONE_PLUS_EPS * x[(size_t)i * DIM + d];
#pragma unroll
        for (int c = 0; c < KNN; ++c)
            if (ok[c]) acc += x[(size_t)nb[c] * DIM + d];
        g_h0[(size_t)i * DIM + d] = acc;
    }
}

// ---------------- BatchNorm (training-mode batch stats) ----------------------
__global__ void bn_zero_kernel() {
    int c = blockIdx.x * 256 + threadIdx.x;
    if (c < DIM) { g_scale[c] = 0.f; g_shift[c] = 0.f; }
}

__global__ void bn_stats_kernel() {
    int c  = blockIdx.x * 256 + threadIdx.x;
    int r0 = blockIdx.y * 256;
    float s = 0.f, q = 0.f;
    for (int r = r0; r < r0 + 256; ++r) {
        float v = g_h2[(size_t)r * DIM + c];
        s += v; q += v * v;
    }
    atomicAdd(&g_scale[c], s);
    atomicAdd(&g_shift[c], q);
}

__global__ void bn_finalize_kernel(const float* __restrict__ gamma,
                                   const float* __restrict__ beta) {
    int c = blockIdx.x * 256 + threadIdx.x;
    if (c >= DIM) return;
    const float invN = 1.f / (float)N_PTS;
    float mean = g_scale[c] * invN;
    float var  = g_shift[c] * invN - mean * mean;
    float sc   = gamma[c] * rsqrtf(var + BN_EPS);
    g_scale[c] = sc;
    g_shift[c] = beta[c] - mean * sc;
}

__global__ void bn_apply_kernel() {
    size_t idx = (size_t)blockIdx.x * 256 + threadIdx.x;
    int c = (int)(idx & (DIM - 1));
    g_hn[idx] = g_h2[idx] * g_scale[c] + g_shift[c];
}

// ---------------- launch -----------------------------------------------------
extern "C" void kernel_launch(void* const* d_in, const int* in_sizes, int n_in,
                              void* d_out, int out_size) {
    const float* x     = (const float*)d_in[0];
    const float* w1    = (const float*)d_in[1];
    const float* b1    = (const float*)d_in[2];
    const float* w2    = (const float*)d_in[3];
    const float* b2    = (const float*)d_in[4];
    const float* gamma = (const float*)d_in[5];
    const float* beta  = (const float*)d_in[6];
    const float* wc    = (const float*)d_in[7];
    float* out = (float*)d_out;

    cudaFuncSetAttribute(gemm_mma, cudaFuncAttributeMaxDynamicSharedMemorySize, SMEM_GEMM);

    float *p_xn, *p_sim, *p_h0, *p_h1, *p_h2, *p_hn;
    unsigned short *p_xh, *p_sh, *p_sl, *p_w1h, *p_w1l, *p_w2h, *p_w2l, *p_wch, *p_wcl;
    cudaGetSymbolAddress((void**)&p_xn,  g_xn);
    cudaGetSymbolAddress((void**)&p_sim, g_sim);
    cudaGetSymbolAddress((void**)&p_h0,  g_h0);
    cudaGetSymbolAddress((void**)&p_h1,  g_h1);
    cudaGetSymbolAddress((void**)&p_h2,  g_h2);
    cudaGetSymbolAddress((void**)&p_hn,  g_hn);
    cudaGetSymbolAddress((void**)&p_xh,  g_xh);
    cudaGetSymbolAddress((void**)&p_sh,  g_sh);
    cudaGetSymbolAddress((void**)&p_sl,  g_sl);
    cudaGetSymbolAddress((void**)&p_w1h, g_w1h);
    cudaGetSymbolAddress((void**)&p_w1l, g_w1l);
    cudaGetSymbolAddress((void**)&p_w2h, g_w2h);
    cudaGetSymbolAddress((void**)&p_w2l, g_w2l);
    cudaGetSymbolAddress((void**)&p_wch, g_wch);
    cudaGetSymbolAddress((void**)&p_wcl, g_wcl);

    const size_t nDD = (size_t)DIM * DIM;
    const size_t nCD = (size_t)NCLS * DIM;
    const size_t nND = (size_t)N_PTS * DIM;

    // 1) normalize (fp32 + bf16)
    normalize_kernel<<<N_PTS, 256>>>(x);

    // 2) weight splits
    split_kernel<<<(unsigned)((nDD + 255) / 256), 256>>>(w1, p_w1h, p_w1l, nDD);
    split_kernel<<<(unsigned)((nDD + 255) / 256), 256>>>(w2, p_w2h, p_w2l, nDD);
    split_kernel<<<(unsigned)((nCD + 255) / 256), 256>>>(wc, p_wch, p_wcl, nCD);

    // 3) similarity (bf16 HMMA, symmetric: compute bx<=by, mirror via smem)
    gemm_mma<<<dim3(64, 64), 256, SMEM_GEMM>>>(
        (const __nv_bfloat16*)p_xh, nullptr, (const __nv_bfloat16*)p_xh, nullptr,
        p_sim, N_PTS, N_PTS, DIM, nullptr, 0, 0, 1);

    // 4) top-16 candidates
    topk_kernel<<<N_PTS, 128>>>();

    // 5) exact fp32 rescore -> top-6
    rescore_kernel<<<N_PTS, 256>>>();

    // 6) k-reciprocal + GIN aggregation -> h0
    aggr_kernel<<<N_PTS, 256>>>(x);

    // 7) MLP layer 1 (bf16x3): relu(h0 @ w1^T + b1)
    split_kernel<<<(unsigned)(nND / 256), 256>>>(p_h0, p_sh, p_sl, nND);
    gemm_mma<<<dim3(16, 64), 256, SMEM_GEMM>>>(
        (const __nv_bfloat16*)p_sh, (const __nv_bfloat16*)p_sl,
        (const __nv_bfloat16*)p_w1h, (const __nv_bfloat16*)p_w1l,
        p_h1, N_PTS, DIM, DIM, b1, 1, 1, 0);

    // 8) MLP layer 2 (bf16x3)
    split_kernel<<<(unsigned)(nND / 256), 256>>>(p_h1, p_sh, p_sl, nND);
    gemm_mma<<<dim3(16, 64), 256, SMEM_GEMM>>>(
        (const __nv_bfloat16*)p_sh, (const __nv_bfloat16*)p_sl,
        (const __nv_bfloat16*)p_w2h, (const __nv_bfloat16*)p_w2l,
        p_h2, N_PTS, DIM, DIM, b2, 0, 1, 0);

    // 9) BatchNorm
    bn_zero_kernel<<<(DIM + 255) / 256, 256>>>();
    bn_stats_kernel<<<dim3(DIM / 256, N_PTS / 256), 256>>>();
    bn_finalize_kernel<<<(DIM + 255) / 256, 256>>>(gamma, beta);
    bn_apply_kernel<<<(unsigned)(nND / 256), 256>>>();

    // 10) classifier (bf16x3): hn @ wc^T -> out [8192, 751]
    split_kernel<<<(unsigned)(nND / 256), 256>>>(p_hn, p_sh, p_sl, nND);
    gemm_mma<<<dim3((NCLS + 127) / 128, 64), 256, SMEM_GEMM>>>(
        (const __nv_bfloat16*)p_sh, (const __nv_bfloat16*)p_sl,
        (const __nv_bfloat16*)p_wch, (const __nv_bfloat16*)p_wcl,
        out, N_PTS, NCLS, DIM, nullptr, 0, 1, 0);
}